// round 4
// baseline (speedup 1.0000x reference)
#include <cuda_runtime.h>

// SmoothRankAP (quick_forward, sigmoid, tau=0.01), B=512. Single fused kernel.
// sigma(x) = 0.5*tanh(x/2)+0.5 with h = scores*50.
//   sim_all(q,i) = 0.5*T_all + 256.5,   T_all = sum_j tanh(h_j - h_i)
//   sim_pos(q,i) = 0.5*(T_pos - tanh(h_q-h_i) + npos) + 0.5,
//                  T_pos = sum_{j in positives(q)} tanh(h_j - h_i)   (j==i gives tanh(0)=0)
// One block per row q (512 blocks x 512 threads); one warp per positive pair.

static constexpr int BB = 512;

__device__ float        g_ap[BB];
__device__ unsigned int g_ticket = 0;   // reset by last block -> deterministic graph replays

__device__ __forceinline__ float tanh_approx(float x) {
    float y;
    asm("tanh.approx.f32 %0, %1;" : "=f"(y) : "f"(x));
    return y;
}

__global__ __launch_bounds__(512) void smoothap_fused_kernel(
    const float* __restrict__ scores,
    const float* __restrict__ target,
    float* __restrict__ out)
{
    __shared__ float    hs[BB];        // scores[q,:] * 50
    __shared__ float    ts[BB];        // target[q,:]
    __shared__ unsigned c_mask[16];    // per-chunk positive ballot masks
    __shared__ int      c_off[16];     // exclusive offsets
    __shared__ int      poslist[BB];
    __shared__ int      npos_s;
    __shared__ float    warp_acc[16];
    __shared__ int      is_last_s;

    const int tid  = threadIdx.x;
    const int wid  = tid >> 5;
    const int lane = tid & 31;
    const int q    = blockIdx.x;

    // ---- stage row q: 128 float4 of scores + 128 float4 of target ----
    if (tid < 128) {
        float4 v = reinterpret_cast<const float4*>(scores + (size_t)q * BB)[tid];
        hs[4 * tid + 0] = v.x * 50.0f; hs[4 * tid + 1] = v.y * 50.0f;
        hs[4 * tid + 2] = v.z * 50.0f; hs[4 * tid + 3] = v.w * 50.0f;
    } else if (tid < 256) {
        const int k = tid - 128;
        float4 w = reinterpret_cast<const float4*>(target + (size_t)q * BB)[k];
        ts[4 * k + 0] = w.x; ts[4 * k + 1] = w.y;
        ts[4 * k + 2] = w.z; ts[4 * k + 3] = w.w;
    }
    __syncthreads();

    // ---- positive compaction: warp w owns chunk w (16 chunks of 32) ----
    {
        unsigned m = __ballot_sync(0xffffffffu, ts[wid * 32 + lane] > 0.5f);
        if (lane == 0) c_mask[wid] = m;
    }
    __syncthreads();
    if (wid == 0) {                         // warp-shuffle exclusive scan of 16 counts
        unsigned mm = (lane < 16) ? c_mask[lane] : 0u;
        int cnt = __popc(mm);
        int incl = cnt;
        #pragma unroll
        for (int o = 1; o < 16; o <<= 1) {
            int n = __shfl_up_sync(0xffffffffu, incl, o);
            if (lane >= o) incl += n;
        }
        if (lane < 16) c_off[lane] = incl - cnt;
        if (lane == 15) npos_s = incl;
    }
    __syncthreads();
    {
        unsigned mm = c_mask[wid];
        if ((mm >> lane) & 1u)
            poslist[c_off[wid] + __popc(mm & ((1u << lane) - 1u))] = wid * 32 + lane;
    }

    // ---- per-lane register cache of h ----
    float hreg[16];
    #pragma unroll
    for (int k = 0; k < 16; ++k) hreg[k] = hs[k * 32 + lane];
    __syncthreads();                        // poslist visible

    const int   npos = npos_s;              // >= 1 (diagonal always positive)
    const float fnp  = (float)npos;
    const float hq   = hs[q];
    const float hpos0 = (lane < npos) ? hs[poslist[lane]] : 0.0f;

    float acc = 0.0f;                       // meaningful on lane 0
    for (int pi = wid; pi < npos; pi += 16) {
        const float hi = hs[poslist[pi]];

        float a = 0.0f;
        #pragma unroll
        for (int k = 0; k < 16; ++k) a += tanh_approx(hreg[k] - hi);

        float p = (lane < npos) ? tanh_approx(hpos0 - hi) : 0.0f;
        for (int l = lane + 32; l < npos; l += 32)      // cold path: npos > 32
            p += tanh_approx(hs[poslist[l]] - hi);

        #pragma unroll
        for (int o = 16; o; o >>= 1) {
            a += __shfl_xor_sync(0xffffffffu, a, o);
            p += __shfl_xor_sync(0xffffffffu, p, o);
        }
        if (lane == 0) {
            const float thq = tanh_approx(hq - hi);
            acc += __fdividef(0.5f * (p - thq + fnp) + 0.5f, 0.5f * a + 256.5f);
        }
    }

    if (lane == 0) warp_acc[wid] = acc;
    __syncthreads();

    if (wid == 0) {                         // warp-shuffle sum of 16 partials
        float g = (lane < 16) ? warp_acc[lane] : 0.0f;
        #pragma unroll
        for (int o = 8; o; o >>= 1) g += __shfl_xor_sync(0xffffffffu, g, o);
        if (lane == 0) {
            g_ap[q] = __fdividef(g, fnp);
            __threadfence();                // publish before ticket
            unsigned tk = atomicAdd(&g_ticket, 1u);
            is_last_s = (tk == (unsigned)(gridDim.x - 1));
        }
    }
    __syncthreads();

    // ---- last block: deterministic final reduction ----
    if (is_last_s) {
        float v = (tid < 256) ? (__ldcg(&g_ap[tid]) + __ldcg(&g_ap[tid + 256])) : 0.0f;
        #pragma unroll
        for (int o = 16; o; o >>= 1) v += __shfl_xor_sync(0xffffffffu, v, o);
        if (lane == 0) warp_acc[wid] = v;
        __syncthreads();
        if (wid == 0) {
            float s = (lane < 16) ? warp_acc[lane] : 0.0f;
            #pragma unroll
            for (int o = 8; o; o >>= 1) s += __shfl_xor_sync(0xffffffffu, s, o);
            if (lane == 0) {
                out[0] = 1.0f - s * (1.0f / (float)BB);
                g_ticket = 0;               // reset for next graph replay
            }
        }
    }
}

extern "C" void kernel_launch(void* const* d_in, const int* in_sizes, int n_in,
                              void* d_out, int out_size)
{
    const float* scores = (const float*)d_in[0];
    const float* target = (const float*)d_in[1];
    smoothap_fused_kernel<<<BB, 512>>>(scores, target, (float*)d_out);
}

// round 5
// speedup vs baseline: 1.0299x; 1.0299x over previous
#include <cuda_runtime.h>

// SmoothRankAP (quick_forward, sigmoid, tau=0.01), B=512. Single fused kernel.
// sigma(x) = 0.5*tanh(x/2)+0.5 with h = scores*50.
//   sim_all(q,i) = 0.5*T_all + 256.5,   T_all = sum_j tanh(h_j - h_i)
//   sim_pos(q,i) = 0.5*(T_pos - tanh(h_q-h_i) + npos) + 0.5,
//                  T_pos = sum_{j in positives(q)} tanh(h_j - h_i)
// 512 blocks x 128 threads: small blocks -> ~10 resident blocks/SM -> whole
// grid fits in ONE wave; each warp handles its pairs as a 4-wide quad for ILP.

static constexpr int BB = 512;

__device__ float        g_ap[BB];
__device__ unsigned int g_ticket = 0;   // reset by last block -> deterministic graph replays

__device__ __forceinline__ float tanh_approx(float x) {
    float y;
    asm("tanh.approx.f32 %0, %1;" : "=f"(y) : "f"(x));
    return y;
}

__global__ __launch_bounds__(128) void smoothap_fused_kernel(
    const float* __restrict__ scores,
    const float* __restrict__ target,
    float* __restrict__ out)
{
    __shared__ float    hs[BB];        // scores[q,:] * 50
    __shared__ float    ts[BB];        // target[q,:]
    __shared__ unsigned c_mask[16];    // per-chunk positive ballots
    __shared__ int      c_off[16];     // exclusive offsets
    __shared__ int      poslist[BB];
    __shared__ int      npos_s;
    __shared__ float    warp_acc[4];
    __shared__ int      is_last_s;

    const int tid  = threadIdx.x;
    const int wid  = tid >> 5;         // 0..3
    const int lane = tid & 31;
    const int q    = blockIdx.x;

    // ---- stage row q: each thread one float4 of scores + one of target ----
    {
        float4 v = reinterpret_cast<const float4*>(scores + (size_t)q * BB)[tid];
        float4 w = reinterpret_cast<const float4*>(target + (size_t)q * BB)[tid];
        hs[4 * tid + 0] = v.x * 50.0f; hs[4 * tid + 1] = v.y * 50.0f;
        hs[4 * tid + 2] = v.z * 50.0f; hs[4 * tid + 3] = v.w * 50.0f;
        ts[4 * tid + 0] = w.x; ts[4 * tid + 1] = w.y;
        ts[4 * tid + 2] = w.z; ts[4 * tid + 3] = w.w;
    }
    __syncthreads();

    // ---- positive compaction: warp w owns chunks 4w..4w+3 ----
    #pragma unroll
    for (int k = 0; k < 4; ++k) {
        const int c = 4 * wid + k;
        unsigned m = __ballot_sync(0xffffffffu, ts[c * 32 + lane] > 0.5f);
        if (lane == 0) c_mask[c] = m;
    }
    __syncthreads();
    if (wid == 0) {                     // warp-shuffle exclusive scan of 16 counts
        unsigned mm = (lane < 16) ? c_mask[lane] : 0u;
        int cnt = __popc(mm);
        int incl = cnt;
        #pragma unroll
        for (int o = 1; o < 16; o <<= 1) {
            int n = __shfl_up_sync(0xffffffffu, incl, o);
            if (lane >= o) incl += n;
        }
        if (lane < 16) c_off[lane] = incl - cnt;
        if (lane == 15) npos_s = incl;
    }
    __syncthreads();
    #pragma unroll
    for (int k = 0; k < 4; ++k) {
        const int c = 4 * wid + k;
        unsigned mm = c_mask[c];
        if ((mm >> lane) & 1u)
            poslist[c_off[c] + __popc(mm & ((1u << lane) - 1u))] = c * 32 + lane;
    }

    // ---- per-lane register cache of h ----
    float hreg[16];
    #pragma unroll
    for (int k = 0; k < 16; ++k) hreg[k] = hs[k * 32 + lane];
    __syncthreads();                    // poslist + npos visible

    const int   npos  = npos_s;         // >= 1 (diagonal always positive)
    const float fnp   = (float)npos;
    const float hq    = hs[q];
    const float hpos0 = (lane < npos) ? hs[poslist[lane]] : 0.0f;

    float acc = 0.0f;                   // meaningful on lane 0
    for (int base = wid; base < npos; base += 16) {
        // quad of pairs: base, base+4, base+8, base+12 (inactive slots discarded)
        int   pidx[4];
        float hi[4];
        #pragma unroll
        for (int u = 0; u < 4; ++u) {
            pidx[u] = base + 4 * u;
            hi[u]   = (pidx[u] < npos) ? hs[poslist[pidx[u]]] : 0.0f;
        }

        float a[4] = {0.f, 0.f, 0.f, 0.f};
        #pragma unroll
        for (int k = 0; k < 16; ++k) {
            const float d = hreg[k];
            #pragma unroll
            for (int u = 0; u < 4; ++u) a[u] += tanh_approx(d - hi[u]);
        }

        float p[4];
        #pragma unroll
        for (int u = 0; u < 4; ++u)
            p[u] = (lane < npos) ? tanh_approx(hpos0 - hi[u]) : 0.0f;
        for (int l = lane + 32; l < npos; l += 32) {    // cold path: npos > 32
            const float hl = hs[poslist[l]];
            #pragma unroll
            for (int u = 0; u < 4; ++u) p[u] += tanh_approx(hl - hi[u]);
        }

        #pragma unroll
        for (int o = 16; o; o >>= 1) {
            #pragma unroll
            for (int u = 0; u < 4; ++u) {
                a[u] += __shfl_xor_sync(0xffffffffu, a[u], o);
                p[u] += __shfl_xor_sync(0xffffffffu, p[u], o);
            }
        }
        if (lane == 0) {
            #pragma unroll
            for (int u = 0; u < 4; ++u) {
                if (pidx[u] < npos) {
                    const float thq = tanh_approx(hq - hi[u]);
                    acc += __fdividef(0.5f * (p[u] - thq + fnp) + 0.5f,
                                      0.5f * a[u] + 256.5f);
                }
            }
        }
    }

    if (lane == 0) warp_acc[wid] = acc;
    __syncthreads();

    if (tid == 0) {
        float g = warp_acc[0] + warp_acc[1] + warp_acc[2] + warp_acc[3];
        g_ap[q] = __fdividef(g, fnp);
        __threadfence();                // publish before ticket
        unsigned tk = atomicAdd(&g_ticket, 1u);
        is_last_s = (tk == (unsigned)(gridDim.x - 1));
    }
    __syncthreads();

    // ---- last block: deterministic final reduction ----
    if (is_last_s) {
        float4 v4 = __ldcg(reinterpret_cast<const float4*>(g_ap) + tid);
        float v = (v4.x + v4.y) + (v4.z + v4.w);
        #pragma unroll
        for (int o = 16; o; o >>= 1) v += __shfl_xor_sync(0xffffffffu, v, o);
        if (lane == 0) warp_acc[wid] = v;
        __syncthreads();
        if (tid == 0) {
            float s = (warp_acc[0] + warp_acc[1]) + (warp_acc[2] + warp_acc[3]);
            out[0] = 1.0f - s * (1.0f / (float)BB);
            g_ticket = 0;               // reset for next graph replay
        }
    }
}

extern "C" void kernel_launch(void* const* d_in, const int* in_sizes, int n_in,
                              void* d_out, int out_size)
{
    const float* scores = (const float*)d_in[0];
    const float* target = (const float*)d_in[1];
    smoothap_fused_kernel<<<BB, 128>>>(scores, target, (float*)d_out);
}